// round 6
// baseline (speedup 1.0000x reference)
#include <cuda_runtime.h>
#include <cstdint>
#include <math_constants.h>

#define NMAX 100000
#define CH 64
#define BMAX 512
#define KTOP 30
#define PLEN 1950   // 30 * 65
#define SEGMAX 4096

// ---------------- scratch (static device globals; no allocs allowed) -------
__device__ float g_y[NMAX * CH];     // (x @ W1) * dis[row]  (fp32)
__device__ float g_agg1[NMAX * CH];  // sum of y over incoming edges
__device__ float g_x1[NMAX * CH];
__device__ float g_deg[NMAX];
__device__ float g_dis[NMAX];
__device__ float g_z[NMAX];          // (x1 @ W2) * dis[row]
__device__ float g_agg2[NMAX];
__device__ float g_x2[NMAX];
__device__ int   g_cnt[BMAX];
__device__ int   g_start[BMAX];

// ---------------- K1: degree counts (8-edge batched) ------------------------
__global__ void deg_kernel(const int* __restrict__ row,
                           const int* __restrict__ col, int E) {
    int g = blockIdx.x * blockDim.x + threadIdx.x;
    int e0 = g * 8;
    if (e0 >= E) return;
    int rr[8], cc[8];
    if (e0 + 7 < E) {
        int4 r0 = __ldg((const int4*)row + g * 2);
        int4 r1 = __ldg((const int4*)row + g * 2 + 1);
        int4 c0 = __ldg((const int4*)col + g * 2);
        int4 c1 = __ldg((const int4*)col + g * 2 + 1);
        rr[0]=r0.x; rr[1]=r0.y; rr[2]=r0.z; rr[3]=r0.w;
        rr[4]=r1.x; rr[5]=r1.y; rr[6]=r1.z; rr[7]=r1.w;
        cc[0]=c0.x; cc[1]=c0.y; cc[2]=c0.z; cc[3]=c0.w;
        cc[4]=c1.x; cc[5]=c1.y; cc[6]=c1.z; cc[7]=c1.w;
    } else {
#pragma unroll
        for (int k = 0; k < 8; k++) {
            int e = e0 + k;
            rr[k] = (e < E) ? row[e] : 0;
            cc[k] = (e < E) ? col[e] : 0;
        }
    }
#pragma unroll
    for (int k = 0; k < 8; k++)
        if (rr[k] != cc[k]) atomicAdd(&g_deg[cc[k]], 1.0f);
}

// ---------------- K2: dis = rsqrt(deg + 1) ----------------------------------
__global__ void dis_kernel(int n) {
    int i = blockIdx.x * blockDim.x + threadIdx.x;
    if (i < n) g_dis[i] = rsqrtf(g_deg[i] + 1.0f);
}

// ---------------- K3: y = (x @ W1) * dis[row] -------------------------------
#define GEMM_TR 128
#define XPITCH 132
#define GEMM_SMEM ((GEMM_TR * XPITCH + 128 * 64) * 4)

__global__ void gemm1_kernel(const float* __restrict__ x,
                             const float* __restrict__ W, int n) {
    extern __shared__ float smem[];
    float* xs = smem;                       // [128][132]
    float* ws = smem + GEMM_TR * XPITCH;    // [128][64]
    int t = threadIdx.x;
    int row0 = blockIdx.x * GEMM_TR;

    for (int i = t; i < 128 * 64 / 4; i += 256)
        ((float4*)ws)[i] = ((const float4*)W)[i];
    for (int i = t; i < GEMM_TR * 32; i += 256) {
        int r = i >> 5, c4 = i & 31;
        float4 v = make_float4(0.f, 0.f, 0.f, 0.f);
        if (row0 + r < n) v = ((const float4*)x)[(size_t)(row0 + r) * 32 + c4];
        *(float4*)&xs[r * XPITCH + c4 * 4] = v;
    }
    __syncthreads();

    int tx = t & 7;
    int ty = t >> 3;
    float acc[4][8];
#pragma unroll
    for (int i = 0; i < 4; i++)
#pragma unroll
        for (int j = 0; j < 8; j++) acc[i][j] = 0.f;

#pragma unroll 4
    for (int k = 0; k < 128; k++) {
        float4 b0 = *(float4*)&ws[k * 64 + tx * 8];
        float4 b1 = *(float4*)&ws[k * 64 + tx * 8 + 4];
        float bb[8] = {b0.x, b0.y, b0.z, b0.w, b1.x, b1.y, b1.z, b1.w};
        float aa[4];
#pragma unroll
        for (int i = 0; i < 4; i++) aa[i] = xs[(ty * 4 + i) * XPITCH + k];
#pragma unroll
        for (int i = 0; i < 4; i++)
#pragma unroll
            for (int j = 0; j < 8; j++) acc[i][j] += aa[i] * bb[j];
    }

#pragma unroll
    for (int i = 0; i < 4; i++) {
        int r = row0 + ty * 4 + i;
        if (r < n) {
            float d = g_dis[r];
            *(float4*)&g_y[(size_t)r * 64 + tx * 8] =
                make_float4(acc[i][0] * d, acc[i][1] * d,
                            acc[i][2] * d, acc[i][3] * d);
            *(float4*)&g_y[(size_t)r * 64 + tx * 8 + 4] =
                make_float4(acc[i][4] * d, acc[i][5] * d,
                            acc[i][6] * d, acc[i][7] * d);
        }
    }
}

// ---------------- K4: edge aggregation conv1 (8-edge batched, MLP=8) --------
__global__ void __launch_bounds__(256, 4)
agg1_kernel(const int* __restrict__ row,
            const int* __restrict__ col, int E) {
    int t = blockIdx.x * blockDim.x + threadIdx.x;
    int g = t >> 4;           // 8-edge group
    int sub = t & 15;         // 16B chunk within the 64-ch row
    int e0 = g * 8;
    if (e0 >= E) return;

    int rr[8], cc[8];
    if (e0 + 7 < E) {
        int4 r0 = __ldg((const int4*)row + g * 2);
        int4 r1 = __ldg((const int4*)row + g * 2 + 1);
        int4 c0 = __ldg((const int4*)col + g * 2);
        int4 c1 = __ldg((const int4*)col + g * 2 + 1);
        rr[0]=r0.x; rr[1]=r0.y; rr[2]=r0.z; rr[3]=r0.w;
        rr[4]=r1.x; rr[5]=r1.y; rr[6]=r1.z; rr[7]=r1.w;
        cc[0]=c0.x; cc[1]=c0.y; cc[2]=c0.z; cc[3]=c0.w;
        cc[4]=c1.x; cc[5]=c1.y; cc[6]=c1.z; cc[7]=c1.w;
    } else {
#pragma unroll
        for (int k = 0; k < 8; k++) {
            int e = e0 + k;
            rr[k] = (e < E) ? __ldg(row + e) : 0;
            cc[k] = (e < E) ? __ldg(col + e) : 0;
        }
    }

    const float4* yb = (const float4*)g_y;
    float4 v[8];
    bool p[8];
#pragma unroll
    for (int k = 0; k < 8; k++) {
        p[k] = (rr[k] != cc[k]);
        if (p[k]) v[k] = __ldg(yb + (size_t)rr[k] * 16 + sub);
    }
#pragma unroll
    for (int k = 0; k < 8; k++) {
        if (p[k])
            atomicAdd((float4*)&g_agg1[(size_t)cc[k] * 64 + sub * 4], v[k]);
    }
}

// ---------------- K5: x1 = tanh(dis*(agg1 + y) + b1); z = (x1.W2)*dis -------
__global__ void node1_kernel(const float* __restrict__ W2,
                             const float* __restrict__ b1, int n) {
    int gt = blockIdx.x * blockDim.x + threadIdx.x;
    int node = gt >> 5;
    int lane = gt & 31;
    if (node >= n) return;
    float dc = g_dis[node];
    size_t base = (size_t)node * 64 + lane * 2;
    float2 yv = *(const float2*)&g_y[base];
    float2 ag = *(const float2*)&g_agg1[base];
    float2 bb = *(const float2*)&b1[lane * 2];
    float v0 = tanhf((ag.x + yv.x) * dc + bb.x);
    float v1 = tanhf((ag.y + yv.y) * dc + bb.y);
    *(float2*)&g_x1[base] = make_float2(v0, v1);
    float2 w2 = *(const float2*)&W2[lane * 2];
    float dot = v0 * w2.x + v1 * w2.y;
#pragma unroll
    for (int off = 16; off; off >>= 1) dot += __shfl_xor_sync(~0u, dot, off);
    if (lane == 0) g_z[node] = dot * dc;
}

// ---------------- K6: edge aggregation conv2 (8-edge batched, MLP=8) --------
__global__ void agg2_kernel(const int* __restrict__ row,
                            const int* __restrict__ col, int E) {
    int g = blockIdx.x * blockDim.x + threadIdx.x;
    int e0 = g * 8;
    if (e0 >= E) return;
    int rr[8], cc[8];
    if (e0 + 7 < E) {
        int4 r0 = __ldg((const int4*)row + g * 2);
        int4 r1 = __ldg((const int4*)row + g * 2 + 1);
        int4 c0 = __ldg((const int4*)col + g * 2);
        int4 c1 = __ldg((const int4*)col + g * 2 + 1);
        rr[0]=r0.x; rr[1]=r0.y; rr[2]=r0.z; rr[3]=r0.w;
        rr[4]=r1.x; rr[5]=r1.y; rr[6]=r1.z; rr[7]=r1.w;
        cc[0]=c0.x; cc[1]=c0.y; cc[2]=c0.z; cc[3]=c0.w;
        cc[4]=c1.x; cc[5]=c1.y; cc[6]=c1.z; cc[7]=c1.w;
    } else {
#pragma unroll
        for (int k = 0; k < 8; k++) {
            int e = e0 + k;
            rr[k] = (e < E) ? row[e] : 0;
            cc[k] = (e < E) ? col[e] : 0;
        }
    }
    float zv[8];
    bool p[8];
#pragma unroll
    for (int k = 0; k < 8; k++) {
        p[k] = (rr[k] != cc[k]);
        if (p[k]) zv[k] = __ldg(&g_z[rr[k]]);
    }
#pragma unroll
    for (int k = 0; k < 8; k++)
        if (p[k]) atomicAdd(&g_agg2[cc[k]], zv[k]);
}

// ---------------- K7: x2 = tanh(dis*(agg2 + z) + b2); batch counts ----------
__global__ void node2_kernel(const float* __restrict__ b2,
                             const int* __restrict__ batch, int n) {
    int i = blockIdx.x * blockDim.x + threadIdx.x;
    if (i >= n) return;
    float dc = g_dis[i];
    g_x2[i] = tanhf((g_agg2[i] + g_z[i]) * dc + b2[0]);
    atomicAdd(&g_cnt[batch[i]], 1);
}

// ---------------- K8: exclusive scan of counts -> segment starts ------------
__global__ void scan_kernel(int B) {
    __shared__ int s[BMAX];
    int t = threadIdx.x;
    int v = (t < B) ? g_cnt[t] : 0;
    s[t] = v;
    __syncthreads();
    for (int off = 1; off < BMAX; off <<= 1) {
        int u = (t >= off) ? s[t - off] : 0;
        __syncthreads();
        s[t] += u;
        __syncthreads();
    }
    if (t < B) g_start[t] = s[t] - v;
}

// ---------------- K9: fused sort-pool(top-30) + CNN head + MLP + logsoftmax -
__global__ void head_kernel(const float* __restrict__ w3, const float* __restrict__ b3,
                            const float* __restrict__ w4, const float* __restrict__ b4,
                            const float* __restrict__ fw1, const float* __restrict__ fb1,
                            const float* __restrict__ fw2, const float* __restrict__ fb2,
                            float* __restrict__ out, int B) {
    __shared__ float sc[SEGMAX];
    __shared__ int sel[KTOP];
    __shared__ float p[PLEN];
    __shared__ float c3[320];
    __shared__ float pl[160];
    __shared__ float h[192];
    __shared__ float ll[128];
    __shared__ float o[18];
    __shared__ unsigned long long redk[256];

    int g = blockIdx.x;
    int t = threadIdx.x;
    int start = g_start[g];
    int cnt = min(g_cnt[g], SEGMAX);
    int ksel = min(cnt, KTOP);

    for (int i = t; i < cnt; i += 256) sc[i] = g_x2[start + i];
    __syncthreads();

    // iterative stable top-K: max score, tie -> lowest index (matches lexsort)
    for (int j = 0; j < ksel; j++) {
        unsigned long long best = 0ull;
        for (int i = t; i < cnt; i += 256) {
            unsigned u = __float_as_uint(sc[i]);
            u = (u & 0x80000000u) ? ~u : (u | 0x80000000u);
            unsigned long long key =
                ((unsigned long long)u << 32) | (unsigned)(~i);
            if (key > best) best = key;
        }
        redk[t] = best;
        __syncthreads();
        for (int off = 128; off; off >>= 1) {
            if (t < off) redk[t] = max(redk[t], redk[t + off]);
            __syncthreads();
        }
        int pos = (int)(~(unsigned)(redk[0] & 0xFFFFFFFFull));
        if (t == 0) {
            sel[j] = start + pos;
            sc[pos] = -CUDART_INF_F;
        }
        __syncthreads();
    }

    for (int idx = t; idx < PLEN; idx += 256) {
        int j = idx / 65, c = idx % 65;
        float v = 0.f;
        if (j < ksel) {
            int node = sel[j];
            v = (c < 64) ? g_x1[(size_t)node * 64 + c] : g_x2[node];
        }
        p[idx] = v;
    }
    __syncthreads();

    for (int idx = t; idx < 320; idx += 256) {
        int oc = idx / 20, tt = idx % 20;
        float s = b3[oc];
        const float* w = w3 + oc * 97;
        const float* pp = p + tt * 97;
#pragma unroll 1
        for (int i = 0; i < 97; i++) s += pp[i] * w[i];
        c3[oc * 20 + tt] = fmaxf(s, 0.f);
    }
    __syncthreads();

    for (int idx = t; idx < 160; idx += 256) {
        int oc = idx / 10, tt = idx % 10;
        pl[idx] = fmaxf(c3[oc * 20 + 2 * tt], c3[oc * 20 + 2 * tt + 1]);
    }
    __syncthreads();

    for (int idx = t; idx < 192; idx += 256) {
        int oc = idx / 6, tt = idx % 6;
        float s = b4[oc];
#pragma unroll
        for (int ic = 0; ic < 16; ic++)
#pragma unroll
            for (int i = 0; i < 5; i++)
                s += pl[ic * 10 + tt + i] * w4[oc * 80 + ic * 5 + i];
        h[idx] = fmaxf(s, 0.f);
    }
    __syncthreads();

    for (int j = t; j < 128; j += 256) {
        float s = fb1[j];
#pragma unroll 4
        for (int i = 0; i < 192; i++) s += h[i] * fw1[i * 128 + j];
        float r = fmaxf(s, 0.f);
        ll[j] = r;
        out[(size_t)2 * B * 18 + (size_t)g * 128 + j] = r;
    }
    __syncthreads();

    for (int j = t; j < 18; j += 256) {
        float s = fb2[j];
#pragma unroll 4
        for (int i = 0; i < 128; i++) s += ll[i] * fw2[i * 18 + j];
        o[j] = s;
        out[(size_t)B * 18 + (size_t)g * 18 + j] = s;
    }
    __syncthreads();

    if (t == 0) {
        float m = o[0];
        for (int j = 1; j < 18; j++) m = fmaxf(m, o[j]);
        float se = 0.f;
        for (int j = 0; j < 18; j++) se += expf(o[j] - m);
        float lse = logf(se) + m;
        for (int j = 0; j < 18; j++) out[(size_t)g * 18 + j] = o[j] - lse;
    }
}

// ---------------- launch ----------------------------------------------------
extern "C" void kernel_launch(void* const* d_in, const int* in_sizes, int n_in,
                              void* d_out, int out_size) {
    const float* x    = (const float*)d_in[0];
    const int* ei     = (const int*)d_in[1];
    const int* batch  = (const int*)d_in[2];
    const float* W1   = (const float*)d_in[4];
    const float* b1   = (const float*)d_in[5];
    const float* W2   = (const float*)d_in[6];
    const float* b2   = (const float*)d_in[7];
    const float* w3   = (const float*)d_in[8];
    const float* b3   = (const float*)d_in[9];
    const float* w4   = (const float*)d_in[10];
    const float* b4   = (const float*)d_in[11];
    const float* fw1  = (const float*)d_in[12];
    const float* fb1  = (const float*)d_in[13];
    const float* fw2  = (const float*)d_in[14];
    const float* fb2  = (const float*)d_in[15];
    float* out = (float*)d_out;

    int n = in_sizes[0] / 128;
    int E = in_sizes[1] / 2;
    int B = out_size / 164;   // 18 + 18 + 128
    const int* row = ei;
    const int* col = ei + E;
    int EG = (E + 7) / 8;     // 8-edge groups

    void* pa;
    cudaGetSymbolAddress(&pa, g_agg1);
    cudaMemsetAsync(pa, 0, (size_t)n * 64 * sizeof(float), 0);
    cudaGetSymbolAddress(&pa, g_agg2);
    cudaMemsetAsync(pa, 0, (size_t)n * sizeof(float), 0);
    cudaGetSymbolAddress(&pa, g_deg);
    cudaMemsetAsync(pa, 0, (size_t)n * sizeof(float), 0);
    cudaGetSymbolAddress(&pa, g_cnt);
    cudaMemsetAsync(pa, 0, (size_t)B * sizeof(int), 0);

    deg_kernel<<<(EG + 255) / 256, 256>>>(row, col, E);
    dis_kernel<<<(n + 255) / 256, 256>>>(n);

    cudaFuncSetAttribute(gemm1_kernel,
                         cudaFuncAttributeMaxDynamicSharedMemorySize, GEMM_SMEM);
    gemm1_kernel<<<(n + GEMM_TR - 1) / GEMM_TR, 256, GEMM_SMEM>>>(x, W1, n);

    {
        long long tot = (long long)EG * 16;
        int blocks = (int)((tot + 255) / 256);
        agg1_kernel<<<blocks, 256>>>(row, col, E);
    }

    node1_kernel<<<(n * 32 + 255) / 256, 256>>>(W2, b1, n);
    agg2_kernel<<<(EG + 255) / 256, 256>>>(row, col, E);
    node2_kernel<<<(n + 255) / 256, 256>>>(b2, batch, n);
    scan_kernel<<<1, BMAX>>>(B);
    head_kernel<<<B, 256>>>(w3, b3, w4, b4, fw1, fb1, fw2, fb2, out, B);
}

// round 7
// speedup vs baseline: 1.0158x; 1.0158x over previous
#include <cuda_runtime.h>
#include <cstdint>
#include <math_constants.h>

#define NMAX 100000
#define CH 64
#define BMAX 512
#define KTOP 30
#define PLEN 1950   // 30 * 65
#define SEGMAX 4096

// ---------------- scratch (static device globals; no allocs allowed) -------
__device__ float g_y[NMAX * CH];     // (x @ W1) * dis[row]  (fp32)
__device__ float g_agg1[NMAX * CH];  // seeded with y, then += y over edges
__device__ float g_x1[NMAX * CH];
__device__ float g_deg[NMAX];
__device__ float g_dis[NMAX];
__device__ float g_z[NMAX];          // (x1 @ W2) * dis[row]
__device__ float g_agg2[NMAX];
__device__ float g_x2[NMAX];
__device__ int   g_cnt[BMAX];
__device__ int   g_start[BMAX];

// ---------------- K1: degree counts (4-edge batched) ------------------------
__global__ void deg_kernel(const int* __restrict__ row,
                           const int* __restrict__ col, int E) {
    int g = blockIdx.x * blockDim.x + threadIdx.x;
    int e0 = g * 4;
    if (e0 >= E) return;
    int rr[4], cc[4];
    if (e0 + 3 < E) {
        int4 r4 = __ldg((const int4*)row + g);
        int4 c4 = __ldg((const int4*)col + g);
        rr[0] = r4.x; rr[1] = r4.y; rr[2] = r4.z; rr[3] = r4.w;
        cc[0] = c4.x; cc[1] = c4.y; cc[2] = c4.z; cc[3] = c4.w;
    } else {
#pragma unroll
        for (int k = 0; k < 4; k++) {
            int e = e0 + k;
            rr[k] = (e < E) ? row[e] : 0;
            cc[k] = (e < E) ? col[e] : 0;
        }
    }
#pragma unroll
    for (int k = 0; k < 4; k++)
        if (rr[k] != cc[k]) atomicAdd(&g_deg[cc[k]], 1.0f);
}

// ---------------- K2: dis = rsqrt(deg + 1) ----------------------------------
__global__ void dis_kernel(int n) {
    int i = blockIdx.x * blockDim.x + threadIdx.x;
    if (i < n) g_dis[i] = rsqrtf(g_deg[i] + 1.0f);
}

// ---------------- K3: y = (x @ W1) * dis[row]; agg1 seeded with y -----------
#define GEMM_TR 128
#define XPITCH 132
#define GEMM_SMEM ((GEMM_TR * XPITCH + 128 * 64) * 4)

__global__ void gemm1_kernel(const float* __restrict__ x,
                             const float* __restrict__ W, int n) {
    extern __shared__ float smem[];
    float* xs = smem;                       // [128][132]
    float* ws = smem + GEMM_TR * XPITCH;    // [128][64]
    int t = threadIdx.x;
    int row0 = blockIdx.x * GEMM_TR;

    for (int i = t; i < 128 * 64 / 4; i += 256)
        ((float4*)ws)[i] = ((const float4*)W)[i];
    for (int i = t; i < GEMM_TR * 32; i += 256) {
        int r = i >> 5, c4 = i & 31;
        float4 v = make_float4(0.f, 0.f, 0.f, 0.f);
        if (row0 + r < n) v = ((const float4*)x)[(size_t)(row0 + r) * 32 + c4];
        *(float4*)&xs[r * XPITCH + c4 * 4] = v;
    }
    __syncthreads();

    int tx = t & 7;
    int ty = t >> 3;
    float acc[4][8];
#pragma unroll
    for (int i = 0; i < 4; i++)
#pragma unroll
        for (int j = 0; j < 8; j++) acc[i][j] = 0.f;

#pragma unroll 4
    for (int k = 0; k < 128; k++) {
        float4 b0 = *(float4*)&ws[k * 64 + tx * 8];
        float4 b1 = *(float4*)&ws[k * 64 + tx * 8 + 4];
        float bb[8] = {b0.x, b0.y, b0.z, b0.w, b1.x, b1.y, b1.z, b1.w};
        float aa[4];
#pragma unroll
        for (int i = 0; i < 4; i++) aa[i] = xs[(ty * 4 + i) * XPITCH + k];
#pragma unroll
        for (int i = 0; i < 4; i++)
#pragma unroll
            for (int j = 0; j < 8; j++) acc[i][j] += aa[i] * bb[j];
    }

#pragma unroll
    for (int i = 0; i < 4; i++) {
        int r = row0 + ty * 4 + i;
        if (r < n) {
            float d = g_dis[r];
            float4 o0 = make_float4(acc[i][0] * d, acc[i][1] * d,
                                    acc[i][2] * d, acc[i][3] * d);
            float4 o1 = make_float4(acc[i][4] * d, acc[i][5] * d,
                                    acc[i][6] * d, acc[i][7] * d);
            size_t ofs = (size_t)r * 64 + tx * 8;
            *(float4*)&g_y[ofs] = o0;
            *(float4*)&g_y[ofs + 4] = o1;
            *(float4*)&g_agg1[ofs] = o0;       // seed self-term (replaces memset)
            *(float4*)&g_agg1[ofs + 4] = o1;
        }
    }
}

// ---------------- K4: edge aggregation conv1 (4-edge batched, MLP=4) --------
__global__ void agg1_kernel(const int* __restrict__ row,
                            const int* __restrict__ col, int E) {
    int t = blockIdx.x * blockDim.x + threadIdx.x;
    int g = t >> 4;           // 4-edge group
    int sub = t & 15;         // 16B chunk within the 64-ch row
    int e0 = g * 4;
    if (e0 >= E) return;

    int rr[4], cc[4];
    if (e0 + 3 < E) {
        int4 r4 = __ldg((const int4*)row + g);
        int4 c4 = __ldg((const int4*)col + g);
        rr[0] = r4.x; rr[1] = r4.y; rr[2] = r4.z; rr[3] = r4.w;
        cc[0] = c4.x; cc[1] = c4.y; cc[2] = c4.z; cc[3] = c4.w;
    } else {
#pragma unroll
        for (int k = 0; k < 4; k++) {
            int e = e0 + k;
            rr[k] = (e < E) ? __ldg(row + e) : 0;
            cc[k] = (e < E) ? __ldg(col + e) : 0;
        }
    }

    const float4* yb = (const float4*)g_y;
    float4 v[4];
    bool p[4];
#pragma unroll
    for (int k = 0; k < 4; k++) {
        p[k] = (rr[k] != cc[k]);
        if (p[k]) v[k] = __ldg(yb + (size_t)rr[k] * 16 + sub);
    }
#pragma unroll
    for (int k = 0; k < 4; k++) {
        if (p[k])
            atomicAdd((float4*)&g_agg1[(size_t)cc[k] * 64 + sub * 4], v[k]);
    }
}

// ---------------- K5: x1 = tanh(agg1*dis + b1); z = (x1.W2)*dis --------------
__global__ void node1_kernel(const float* __restrict__ W2,
                             const float* __restrict__ b1, int n) {
    int gt = blockIdx.x * blockDim.x + threadIdx.x;
    int node = gt >> 5;
    int lane = gt & 31;
    if (node >= n) return;
    float dc = g_dis[node];
    size_t base = (size_t)node * 64 + lane * 2;
    float2 ag = *(const float2*)&g_agg1[base];
    float2 bb = *(const float2*)&b1[lane * 2];
    float v0 = tanhf(ag.x * dc + bb.x);
    float v1 = tanhf(ag.y * dc + bb.y);
    *(float2*)&g_x1[base] = make_float2(v0, v1);
    float2 w2 = *(const float2*)&W2[lane * 2];
    float dot = v0 * w2.x + v1 * w2.y;
#pragma unroll
    for (int off = 16; off; off >>= 1) dot += __shfl_xor_sync(~0u, dot, off);
    if (lane == 0) g_z[node] = dot * dc;
}

// ---------------- K6: edge aggregation conv2 (4-edge batched, MLP=4) --------
__global__ void agg2_kernel(const int* __restrict__ row,
                            const int* __restrict__ col, int E) {
    int g = blockIdx.x * blockDim.x + threadIdx.x;
    int e0 = g * 4;
    if (e0 >= E) return;
    int rr[4], cc[4];
    if (e0 + 3 < E) {
        int4 r4 = __ldg((const int4*)row + g);
        int4 c4 = __ldg((const int4*)col + g);
        rr[0] = r4.x; rr[1] = r4.y; rr[2] = r4.z; rr[3] = r4.w;
        cc[0] = c4.x; cc[1] = c4.y; cc[2] = c4.z; cc[3] = c4.w;
    } else {
#pragma unroll
        for (int k = 0; k < 4; k++) {
            int e = e0 + k;
            rr[k] = (e < E) ? row[e] : 0;
            cc[k] = (e < E) ? col[e] : 0;
        }
    }
    float zv[4];
    bool p[4];
#pragma unroll
    for (int k = 0; k < 4; k++) {
        p[k] = (rr[k] != cc[k]);
        if (p[k]) zv[k] = __ldg(&g_z[rr[k]]);
    }
#pragma unroll
    for (int k = 0; k < 4; k++)
        if (p[k]) atomicAdd(&g_agg2[cc[k]], zv[k]);
}

// ---------------- K7: x2 = tanh(dis*(agg2 + z) + b2); batch counts ----------
__global__ void node2_kernel(const float* __restrict__ b2,
                             const int* __restrict__ batch, int n) {
    int i = blockIdx.x * blockDim.x + threadIdx.x;
    if (i >= n) return;
    float dc = g_dis[i];
    g_x2[i] = tanhf((g_agg2[i] + g_z[i]) * dc + b2[0]);
    atomicAdd(&g_cnt[batch[i]], 1);
}

// ---------------- K8: exclusive scan of counts -> segment starts ------------
__global__ void scan_kernel(int B) {
    __shared__ int s[BMAX];
    int t = threadIdx.x;
    int v = (t < B) ? g_cnt[t] : 0;
    s[t] = v;
    __syncthreads();
    for (int off = 1; off < BMAX; off <<= 1) {
        int u = (t >= off) ? s[t - off] : 0;
        __syncthreads();
        s[t] += u;
        __syncthreads();
    }
    if (t < B) g_start[t] = s[t] - v;
}

// ---------------- K9: fused sort-pool(top-30) + CNN head + MLP + logsoftmax -
__global__ void head_kernel(const float* __restrict__ w3, const float* __restrict__ b3,
                            const float* __restrict__ w4, const float* __restrict__ b4,
                            const float* __restrict__ fw1, const float* __restrict__ fb1,
                            const float* __restrict__ fw2, const float* __restrict__ fb2,
                            float* __restrict__ out, int B) {
    __shared__ float sc[SEGMAX];
    __shared__ int sel[KTOP];
    __shared__ float p[PLEN];
    __shared__ float c3[320];
    __shared__ float pl[160];
    __shared__ float h[192];
    __shared__ float ll[128];
    __shared__ float o[18];
    __shared__ unsigned long long redw[8];

    int g = blockIdx.x;
    int t = threadIdx.x;
    int lane = t & 31;
    int warp = t >> 5;
    int start = g_start[g];
    int cnt = min(g_cnt[g], SEGMAX);
    int ksel = min(cnt, KTOP);

    for (int i = t; i < cnt; i += 256) sc[i] = g_x2[start + i];
    __syncthreads();

    // iterative stable top-K: max score, tie -> lowest index (matches lexsort)
    // warp-shuffle reduction: 2 syncs per iteration
    for (int j = 0; j < ksel; j++) {
        unsigned long long best = 0ull;
        for (int i = t; i < cnt; i += 256) {
            unsigned u = __float_as_uint(sc[i]);
            u = (u & 0x80000000u) ? ~u : (u | 0x80000000u);
            unsigned long long key =
                ((unsigned long long)u << 32) | (unsigned)(~i);
            if (key > best) best = key;
        }
#pragma unroll
        for (int off = 16; off; off >>= 1) {
            unsigned long long o2 = __shfl_xor_sync(~0u, best, off);
            best = max(best, o2);
        }
        if (lane == 0) redw[warp] = best;
        __syncthreads();
        if (warp == 0) {
            unsigned long long b2 = (lane < 8) ? redw[lane] : 0ull;
#pragma unroll
            for (int off = 4; off; off >>= 1) {
                unsigned long long o2 = __shfl_xor_sync(~0u, b2, off);
                b2 = max(b2, o2);
            }
            if (lane == 0) {
                int pos = (int)(~(unsigned)(b2 & 0xFFFFFFFFull));
                sel[j] = start + pos;
                sc[pos] = -CUDART_INF_F;
            }
        }
        __syncthreads();
    }

    for (int idx = t; idx < PLEN; idx += 256) {
        int j = idx / 65, c = idx % 65;
        float v = 0.f;
        if (j < ksel) {
            int node = sel[j];
            v = (c < 64) ? g_x1[(size_t)node * 64 + c] : g_x2[node];
        }
        p[idx] = v;
    }
    __syncthreads();

    for (int idx = t; idx < 320; idx += 256) {
        int oc = idx / 20, tt = idx % 20;
        float s = b3[oc];
        const float* w = w3 + oc * 97;
        const float* pp = p + tt * 97;
#pragma unroll 1
        for (int i = 0; i < 97; i++) s += pp[i] * w[i];
        c3[oc * 20 + tt] = fmaxf(s, 0.f);
    }
    __syncthreads();

    for (int idx = t; idx < 160; idx += 256) {
        int oc = idx / 10, tt = idx % 10;
        pl[idx] = fmaxf(c3[oc * 20 + 2 * tt], c3[oc * 20 + 2 * tt + 1]);
    }
    __syncthreads();

    for (int idx = t; idx < 192; idx += 256) {
        int oc = idx / 6, tt = idx % 6;
        float s = b4[oc];
#pragma unroll
        for (int ic = 0; ic < 16; ic++)
#pragma unroll
            for (int i = 0; i < 5; i++)
                s += pl[ic * 10 + tt + i] * w4[oc * 80 + ic * 5 + i];
        h[idx] = fmaxf(s, 0.f);
    }
    __syncthreads();

    for (int j = t; j < 128; j += 256) {
        float s = fb1[j];
#pragma unroll 4
        for (int i = 0; i < 192; i++) s += h[i] * fw1[i * 128 + j];
        float r = fmaxf(s, 0.f);
        ll[j] = r;
        out[(size_t)2 * B * 18 + (size_t)g * 128 + j] = r;
    }
    __syncthreads();

    for (int j = t; j < 18; j += 256) {
        float s = fb2[j];
#pragma unroll 4
        for (int i = 0; i < 128; i++) s += ll[i] * fw2[i * 18 + j];
        o[j] = s;
        out[(size_t)B * 18 + (size_t)g * 18 + j] = s;
    }
    __syncthreads();

    if (t == 0) {
        float m = o[0];
        for (int j = 1; j < 18; j++) m = fmaxf(m, o[j]);
        float se = 0.f;
        for (int j = 0; j < 18; j++) se += expf(o[j] - m);
        float lse = logf(se) + m;
        for (int j = 0; j < 18; j++) out[(size_t)g * 18 + j] = o[j] - lse;
    }
}

// ---------------- launch ----------------------------------------------------
extern "C" void kernel_launch(void* const* d_in, const int* in_sizes, int n_in,
                              void* d_out, int out_size) {
    const float* x    = (const float*)d_in[0];
    const int* ei     = (const int*)d_in[1];
    const int* batch  = (const int*)d_in[2];
    const float* W1   = (const float*)d_in[4];
    const float* b1   = (const float*)d_in[5];
    const float* W2   = (const float*)d_in[6];
    const float* b2   = (const float*)d_in[7];
    const float* w3   = (const float*)d_in[8];
    const float* b3   = (const float*)d_in[9];
    const float* w4   = (const float*)d_in[10];
    const float* b4   = (const float*)d_in[11];
    const float* fw1  = (const float*)d_in[12];
    const float* fb1  = (const float*)d_in[13];
    const float* fw2  = (const float*)d_in[14];
    const float* fb2  = (const float*)d_in[15];
    float* out = (float*)d_out;

    int n = in_sizes[0] / 128;
    int E = in_sizes[1] / 2;
    int B = out_size / 164;   // 18 + 18 + 128
    const int* row = ei;
    const int* col = ei + E;
    int EG = (E + 3) / 4;     // 4-edge groups

    void* pa;
    cudaGetSymbolAddress(&pa, g_agg2);
    cudaMemsetAsync(pa, 0, (size_t)n * sizeof(float), 0);
    cudaGetSymbolAddress(&pa, g_deg);
    cudaMemsetAsync(pa, 0, (size_t)n * sizeof(float), 0);
    cudaGetSymbolAddress(&pa, g_cnt);
    cudaMemsetAsync(pa, 0, (size_t)B * sizeof(int), 0);

    deg_kernel<<<(EG + 255) / 256, 256>>>(row, col, E);
    dis_kernel<<<(n + 255) / 256, 256>>>(n);

    cudaFuncSetAttribute(gemm1_kernel,
                         cudaFuncAttributeMaxDynamicSharedMemorySize, GEMM_SMEM);
    gemm1_kernel<<<(n + GEMM_TR - 1) / GEMM_TR, 256, GEMM_SMEM>>>(x, W1, n);

    {
        long long tot = (long long)EG * 16;
        int blocks = (int)((tot + 255) / 256);
        agg1_kernel<<<blocks, 256>>>(row, col, E);
    }

    node1_kernel<<<(n * 32 + 255) / 256, 256>>>(W2, b1, n);
    agg2_kernel<<<(EG + 255) / 256, 256>>>(row, col, E);
    node2_kernel<<<(n + 255) / 256, 256>>>(b2, batch, n);
    scan_kernel<<<1, BMAX>>>(B);
    head_kernel<<<B, 256>>>(w3, b3, w4, b4, fw1, fb1, fw2, fb2, out, B);
}

// round 8
// speedup vs baseline: 1.0207x; 1.0049x over previous
#include <cuda_runtime.h>
#include <cstdint>
#include <math_constants.h>

#define NMAX 100000
#define CH 64
#define BMAX 512
#define KTOP 30
#define PLEN 1950   // 30 * 65
#define SEGMAX 4096

#define FMA_F32X2(d, a, b, c) \
    asm("fma.rn.f32x2 %0, %1, %2, %3;" : "=l"(d) : "l"(a), "l"(b), "l"(c))
#define PACK_DUP_F32X2(d, a) \
    asm("mov.b64 %0, {%1, %1};" : "=l"(d) : "f"(a))
#define UNPACK_F32X2(lo, hi, in) \
    asm("mov.b64 {%0, %1}, %2;" : "=f"(lo), "=f"(hi) : "l"(in))

// ---------------- scratch (static device globals; no allocs allowed) -------
__device__ float g_y[NMAX * CH];     // (x @ W1) * dis[row]  (fp32)
__device__ float g_agg1[NMAX * CH];  // seeded with y, then += y over edges
__device__ float g_x1[NMAX * CH];
__device__ float g_deg[NMAX];
__device__ float g_z[NMAX];          // (x1 @ W2) * dis[row]
__device__ float g_agg2[NMAX];
__device__ float g_x2[NMAX];
__device__ int   g_cnt[BMAX];
__device__ int   g_start[BMAX];

// ---------------- K1: degree counts (4-edge batched) ------------------------
__global__ void deg_kernel(const int* __restrict__ row,
                           const int* __restrict__ col, int E) {
    int g = blockIdx.x * blockDim.x + threadIdx.x;
    int e0 = g * 4;
    if (e0 >= E) return;
    int rr[4], cc[4];
    if (e0 + 3 < E) {
        int4 r4 = __ldg((const int4*)row + g);
        int4 c4 = __ldg((const int4*)col + g);
        rr[0] = r4.x; rr[1] = r4.y; rr[2] = r4.z; rr[3] = r4.w;
        cc[0] = c4.x; cc[1] = c4.y; cc[2] = c4.z; cc[3] = c4.w;
    } else {
#pragma unroll
        for (int k = 0; k < 4; k++) {
            int e = e0 + k;
            rr[k] = (e < E) ? row[e] : 0;
            cc[k] = (e < E) ? col[e] : 0;
        }
    }
#pragma unroll
    for (int k = 0; k < 4; k++)
        if (rr[k] != cc[k]) atomicAdd(&g_deg[cc[k]], 1.0f);
}

// ---------------- K3: y = (x @ W1) * rsqrt(deg+1); agg1 seeded with y ------
#define GEMM_TR 128
#define XPITCH 132
#define GEMM_SMEM ((GEMM_TR * XPITCH + 128 * 64) * 4)

__global__ void gemm1_kernel(const float* __restrict__ x,
                             const float* __restrict__ W, int n) {
    extern __shared__ float smem[];
    float* xs = smem;                       // [128][132]
    float* ws = smem + GEMM_TR * XPITCH;    // [128][64]
    int t = threadIdx.x;
    int row0 = blockIdx.x * GEMM_TR;

    for (int i = t; i < 128 * 64 / 4; i += 256)
        ((float4*)ws)[i] = ((const float4*)W)[i];
    for (int i = t; i < GEMM_TR * 32; i += 256) {
        int r = i >> 5, c4 = i & 31;
        float4 v = make_float4(0.f, 0.f, 0.f, 0.f);
        if (row0 + r < n) v = ((const float4*)x)[(size_t)(row0 + r) * 32 + c4];
        *(float4*)&xs[r * XPITCH + c4 * 4] = v;
    }
    __syncthreads();

    int tx = t & 7;      // 8 col-groups of 8 cols (= 4 f32x2 pairs)
    int ty = t >> 3;     // 32 row-groups of 4 rows
    unsigned long long acc[4][4];
#pragma unroll
    for (int i = 0; i < 4; i++)
#pragma unroll
        for (int j = 0; j < 4; j++) acc[i][j] = 0ull;   // two packed +0.0f

#pragma unroll 4
    for (int k = 0; k < 128; k++) {
        const unsigned long long* w64 =
            (const unsigned long long*)(ws + k * 64 + tx * 8);
        unsigned long long b0 = w64[0], b1 = w64[1], b2 = w64[2], b3 = w64[3];
#pragma unroll
        for (int i = 0; i < 4; i++) {
            float a = xs[(ty * 4 + i) * XPITCH + k];
            unsigned long long ad;
            PACK_DUP_F32X2(ad, a);
            FMA_F32X2(acc[i][0], ad, b0, acc[i][0]);
            FMA_F32X2(acc[i][1], ad, b1, acc[i][1]);
            FMA_F32X2(acc[i][2], ad, b2, acc[i][2]);
            FMA_F32X2(acc[i][3], ad, b3, acc[i][3]);
        }
    }

#pragma unroll
    for (int i = 0; i < 4; i++) {
        int r = row0 + ty * 4 + i;
        if (r < n) {
            float d = rsqrtf(g_deg[r] + 1.0f);
            float f[8];
#pragma unroll
            for (int j = 0; j < 4; j++)
                UNPACK_F32X2(f[2 * j], f[2 * j + 1], acc[i][j]);
            float4 o0 = make_float4(f[0] * d, f[1] * d, f[2] * d, f[3] * d);
            float4 o1 = make_float4(f[4] * d, f[5] * d, f[6] * d, f[7] * d);
            size_t ofs = (size_t)r * 64 + tx * 8;
            *(float4*)&g_y[ofs] = o0;
            *(float4*)&g_y[ofs + 4] = o1;
            *(float4*)&g_agg1[ofs] = o0;       // seed self-term (replaces memset)
            *(float4*)&g_agg1[ofs + 4] = o1;
        }
    }
}

// ---------------- K4: edge aggregation conv1 (4-edge batched, MLP=4) --------
__global__ void agg1_kernel(const int* __restrict__ row,
                            const int* __restrict__ col, int E) {
    int t = blockIdx.x * blockDim.x + threadIdx.x;
    int g = t >> 4;           // 4-edge group
    int sub = t & 15;         // 16B chunk within the 64-ch row
    int e0 = g * 4;
    if (e0 >= E) return;

    int rr[4], cc[4];
    if (e0 + 3 < E) {
        int4 r4 = __ldg((const int4*)row + g);
        int4 c4 = __ldg((const int4*)col + g);
        rr[0] = r4.x; rr[1] = r4.y; rr[2] = r4.z; rr[3] = r4.w;
        cc[0] = c4.x; cc[1] = c4.y; cc[2] = c4.z; cc[3] = c4.w;
    } else {
#pragma unroll
        for (int k = 0; k < 4; k++) {
            int e = e0 + k;
            rr[k] = (e < E) ? __ldg(row + e) : 0;
            cc[k] = (e < E) ? __ldg(col + e) : 0;
        }
    }

    const float4* yb = (const float4*)g_y;
    float4 v[4];
    bool p[4];
#pragma unroll
    for (int k = 0; k < 4; k++) {
        p[k] = (rr[k] != cc[k]);
        if (p[k]) v[k] = __ldg(yb + (size_t)rr[k] * 16 + sub);
    }
#pragma unroll
    for (int k = 0; k < 4; k++) {
        if (p[k])
            atomicAdd((float4*)&g_agg1[(size_t)cc[k] * 64 + sub * 4], v[k]);
    }
}

// ---------------- K5: x1 = tanh(agg1*dis + b1); z = (x1.W2)*dis --------------
__global__ void node1_kernel(const float* __restrict__ W2,
                             const float* __restrict__ b1, int n) {
    int gt = blockIdx.x * blockDim.x + threadIdx.x;
    int node = gt >> 5;
    int lane = gt & 31;
    if (node >= n) return;
    float dc = rsqrtf(g_deg[node] + 1.0f);
    size_t base = (size_t)node * 64 + lane * 2;
    float2 ag = *(const float2*)&g_agg1[base];
    float2 bb = *(const float2*)&b1[lane * 2];
    float v0 = tanhf(ag.x * dc + bb.x);
    float v1 = tanhf(ag.y * dc + bb.y);
    *(float2*)&g_x1[base] = make_float2(v0, v1);
    float2 w2 = *(const float2*)&W2[lane * 2];
    float dot = v0 * w2.x + v1 * w2.y;
#pragma unroll
    for (int off = 16; off; off >>= 1) dot += __shfl_xor_sync(~0u, dot, off);
    if (lane == 0) g_z[node] = dot * dc;
}

// ---------------- K6: edge aggregation conv2 (4-edge batched, MLP=4) --------
__global__ void agg2_kernel(const int* __restrict__ row,
                            const int* __restrict__ col, int E) {
    int g = blockIdx.x * blockDim.x + threadIdx.x;
    int e0 = g * 4;
    if (e0 >= E) return;
    int rr[4], cc[4];
    if (e0 + 3 < E) {
        int4 r4 = __ldg((const int4*)row + g);
        int4 c4 = __ldg((const int4*)col + g);
        rr[0] = r4.x; rr[1] = r4.y; rr[2] = r4.z; rr[3] = r4.w;
        cc[0] = c4.x; cc[1] = c4.y; cc[2] = c4.z; cc[3] = c4.w;
    } else {
#pragma unroll
        for (int k = 0; k < 4; k++) {
            int e = e0 + k;
            rr[k] = (e < E) ? row[e] : 0;
            cc[k] = (e < E) ? col[e] : 0;
        }
    }
    float zv[4];
    bool p[4];
#pragma unroll
    for (int k = 0; k < 4; k++) {
        p[k] = (rr[k] != cc[k]);
        if (p[k]) zv[k] = __ldg(&g_z[rr[k]]);
    }
#pragma unroll
    for (int k = 0; k < 4; k++)
        if (p[k]) atomicAdd(&g_agg2[cc[k]], zv[k]);
}

// ---------------- K7: x2 = tanh(dis*(agg2 + z) + b2); batch counts ----------
__global__ void node2_kernel(const float* __restrict__ b2,
                             const int* __restrict__ batch, int n) {
    int i = blockIdx.x * blockDim.x + threadIdx.x;
    if (i >= n) return;
    float dc = rsqrtf(g_deg[i] + 1.0f);
    g_x2[i] = tanhf((g_agg2[i] + g_z[i]) * dc + b2[0]);
    atomicAdd(&g_cnt[batch[i]], 1);
}

// ---------------- K8: exclusive scan of counts -> segment starts ------------
__global__ void scan_kernel(int B) {
    __shared__ int s[BMAX];
    int t = threadIdx.x;
    int v = (t < B) ? g_cnt[t] : 0;
    s[t] = v;
    __syncthreads();
    for (int off = 1; off < BMAX; off <<= 1) {
        int u = (t >= off) ? s[t - off] : 0;
        __syncthreads();
        s[t] += u;
        __syncthreads();
    }
    if (t < B) g_start[t] = s[t] - v;
}

// ---------------- K9: fused sort-pool(top-30) + CNN head + MLP + logsoftmax -
__global__ void head_kernel(const float* __restrict__ w3, const float* __restrict__ b3,
                            const float* __restrict__ w4, const float* __restrict__ b4,
                            const float* __restrict__ fw1, const float* __restrict__ fb1,
                            const float* __restrict__ fw2, const float* __restrict__ fb2,
                            float* __restrict__ out, int B) {
    __shared__ float sc[SEGMAX];
    __shared__ int sel[KTOP];
    __shared__ float p[PLEN];
    __shared__ float c3[320];
    __shared__ float pl[160];
    __shared__ float h[192];
    __shared__ float ll[128];
    __shared__ float o[18];
    __shared__ unsigned long long redw[8];

    int g = blockIdx.x;
    int t = threadIdx.x;
    int lane = t & 31;
    int warp = t >> 5;
    int start = g_start[g];
    int cnt = min(g_cnt[g], SEGMAX);
    int ksel = min(cnt, KTOP);

    for (int i = t; i < cnt; i += 256) sc[i] = g_x2[start + i];
    __syncthreads();

    // iterative stable top-K: max score, tie -> lowest index (matches lexsort)
    for (int j = 0; j < ksel; j++) {
        unsigned long long best = 0ull;
        for (int i = t; i < cnt; i += 256) {
            unsigned u = __float_as_uint(sc[i]);
            u = (u & 0x80000000u) ? ~u : (u | 0x80000000u);
            unsigned long long key =
                ((unsigned long long)u << 32) | (unsigned)(~i);
            if (key > best) best = key;
        }
#pragma unroll
        for (int off = 16; off; off >>= 1) {
            unsigned long long o2 = __shfl_xor_sync(~0u, best, off);
            best = max(best, o2);
        }
        if (lane == 0) redw[warp] = best;
        __syncthreads();
        if (warp == 0) {
            unsigned long long b2 = (lane < 8) ? redw[lane] : 0ull;
#pragma unroll
            for (int off = 4; off; off >>= 1) {
                unsigned long long o2 = __shfl_xor_sync(~0u, b2, off);
                b2 = max(b2, o2);
            }
            if (lane == 0) {
                int pos = (int)(~(unsigned)(b2 & 0xFFFFFFFFull));
                sel[j] = start + pos;
                sc[pos] = -CUDART_INF_F;
            }
        }
        __syncthreads();
    }

    for (int idx = t; idx < PLEN; idx += 256) {
        int j = idx / 65, c = idx % 65;
        float v = 0.f;
        if (j < ksel) {
            int node = sel[j];
            v = (c < 64) ? g_x1[(size_t)node * 64 + c] : g_x2[node];
        }
        p[idx] = v;
    }
    __syncthreads();

    for (int idx = t; idx < 320; idx += 256) {
        int oc = idx / 20, tt = idx % 20;
        float s = b3[oc];
        const float* w = w3 + oc * 97;
        const float* pp = p + tt * 97;
#pragma unroll 1
        for (int i = 0; i < 97; i++) s += pp[i] * w[i];
        c3[oc * 20 + tt] = fmaxf(s, 0.f);
    }
    __syncthreads();

    for (int idx = t; idx < 160; idx += 256) {
        int oc = idx / 10, tt = idx % 10;
        pl[idx] = fmaxf(c3[oc * 20 + 2 * tt], c3[oc * 20 + 2 * tt + 1]);
    }
    __syncthreads();

    for (int idx = t; idx < 192; idx += 256) {
        int oc = idx / 6, tt = idx % 6;
        float s = b4[oc];
#pragma unroll
        for (int ic = 0; ic < 16; ic++)
#pragma unroll
            for (int i = 0; i < 5; i++)
                s += pl[ic * 10 + tt + i] * w4[oc * 80 + ic * 5 + i];
        h[idx] = fmaxf(s, 0.f);
    }
    __syncthreads();

    for (int j = t; j < 128; j += 256) {
        float s = fb1[j];
#pragma unroll 4
        for (int i = 0; i < 192; i++) s += h[i] * fw1[i * 128 + j];
        float r = fmaxf(s, 0.f);
        ll[j] = r;
        out[(size_t)2 * B * 18 + (size_t)g * 128 + j] = r;
    }
    __syncthreads();

    for (int j = t; j < 18; j += 256) {
        float s = fb2[j];
#pragma unroll 4
        for (int i = 0; i < 128; i++) s += ll[i] * fw2[i * 18 + j];
        o[j] = s;
        out[(size_t)B * 18 + (size_t)g * 18 + j] = s;
    }
    __syncthreads();

    if (t == 0) {
        float m = o[0];
        for (int j = 1; j < 18; j++) m = fmaxf(m, o[j]);
        float se = 0.f;
        for (int j = 0; j < 18; j++) se += expf(o[j] - m);
        float lse = logf(se) + m;
        for (int j = 0; j < 18; j++) out[(size_t)g * 18 + j] = o[j] - lse;
    }
}

// ---------------- launch ----------------------------------------------------
extern "C" void kernel_launch(void* const* d_in, const int* in_sizes, int n_in,
                              void* d_out, int out_size) {
    const float* x    = (const float*)d_in[0];
    const int* ei     = (const int*)d_in[1];
    const int* batch  = (const int*)d_in[2];
    const float* W1   = (const float*)d_in[4];
    const float* b1   = (const float*)d_in[5];
    const float* W2   = (const float*)d_in[6];
    const float* b2   = (const float*)d_in[7];
    const float* w3   = (const float*)d_in[8];
    const float* b3   = (const float*)d_in[9];
    const float* w4   = (const float*)d_in[10];
    const float* b4   = (const float*)d_in[11];
    const float* fw1  = (const float*)d_in[12];
    const float* fb1  = (const float*)d_in[13];
    const float* fw2  = (const float*)d_in[14];
    const float* fb2  = (const float*)d_in[15];
    float* out = (float*)d_out;

    int n = in_sizes[0] / 128;
    int E = in_sizes[1] / 2;
    int B = out_size / 164;   // 18 + 18 + 128
    const int* row = ei;
    const int* col = ei + E;
    int EG = (E + 3) / 4;     // 4-edge groups

    void* pa;
    cudaGetSymbolAddress(&pa, g_agg2);
    cudaMemsetAsync(pa, 0, (size_t)n * sizeof(float), 0);
    cudaGetSymbolAddress(&pa, g_deg);
    cudaMemsetAsync(pa, 0, (size_t)n * sizeof(float), 0);
    cudaGetSymbolAddress(&pa, g_cnt);
    cudaMemsetAsync(pa, 0, (size_t)B * sizeof(int), 0);

    deg_kernel<<<(EG + 255) / 256, 256>>>(row, col, E);

    cudaFuncSetAttribute(gemm1_kernel,
                         cudaFuncAttributeMaxDynamicSharedMemorySize, GEMM_SMEM);
    gemm1_kernel<<<(n + GEMM_TR - 1) / GEMM_TR, 256, GEMM_SMEM>>>(x, W1, n);

    {
        long long tot = (long long)EG * 16;
        int blocks = (int)((tot + 255) / 256);
        agg1_kernel<<<blocks, 256>>>(row, col, E);
    }

    node1_kernel<<<(n * 32 + 255) / 256, 256>>>(W2, b1, n);
    agg2_kernel<<<(EG + 255) / 256, 256>>>(row, col, E);
    node2_kernel<<<(n + 255) / 256, 256>>>(b2, batch, n);
    scan_kernel<<<1, BMAX>>>(B);
    head_kernel<<<B, 256>>>(w3, b3, w4, b4, fw1, fb1, fw2, fb2, out, B);
}

// round 9
// speedup vs baseline: 1.0767x; 1.0548x over previous
#include <cuda_runtime.h>
#include <cstdint>
#include <math_constants.h>

#define NMAX 100000
#define CH 64
#define KTOP 30
#define PLEN 1950   // 30 * 65
#define SEGMAX 4096

#define FMA_F32X2(d, a, b, c) \
    asm("fma.rn.f32x2 %0, %1, %2, %3;" : "=l"(d) : "l"(a), "l"(b), "l"(c))
#define PACK_DUP_F32X2(d, a) \
    asm("mov.b64 %0, {%1, %1};" : "=l"(d) : "f"(a))
#define UNPACK_F32X2(lo, hi, in) \
    asm("mov.b64 {%0, %1}, %2;" : "=f"(lo), "=f"(hi) : "l"(in))

// ---------------- scratch (static device globals; no allocs allowed) -------
__device__ float g_y[NMAX * CH];     // (x @ W1) * dis[row]  (fp32)
__device__ float g_agg1[NMAX * CH];  // seeded with y, then += y over edges
__device__ float g_x1[NMAX * CH];
__device__ float g_deg[NMAX];
__device__ float g_z[NMAX];          // (x1 @ W2) * dis[row]
__device__ float g_agg2[NMAX];

// ---------------- K0: zero g_deg and g_agg2 in one launch -------------------
__global__ void zero_kernel(int n) {
    int i = blockIdx.x * blockDim.x + threadIdx.x;
    if (i < n) {
        g_deg[i] = 0.f;
        g_agg2[i] = 0.f;
    }
}

// ---------------- K1: degree counts (4-edge batched) ------------------------
__global__ void deg_kernel(const int* __restrict__ row,
                           const int* __restrict__ col, int E) {
    int g = blockIdx.x * blockDim.x + threadIdx.x;
    int e0 = g * 4;
    if (e0 >= E) return;
    int rr[4], cc[4];
    if (e0 + 3 < E) {
        int4 r4 = __ldg((const int4*)row + g);
        int4 c4 = __ldg((const int4*)col + g);
        rr[0] = r4.x; rr[1] = r4.y; rr[2] = r4.z; rr[3] = r4.w;
        cc[0] = c4.x; cc[1] = c4.y; cc[2] = c4.z; cc[3] = c4.w;
    } else {
#pragma unroll
        for (int k = 0; k < 4; k++) {
            int e = e0 + k;
            rr[k] = (e < E) ? row[e] : 0;
            cc[k] = (e < E) ? col[e] : 0;
        }
    }
#pragma unroll
    for (int k = 0; k < 4; k++)
        if (rr[k] != cc[k]) atomicAdd(&g_deg[cc[k]], 1.0f);
}

// ---------------- K3: y = (x @ W1) * rsqrt(deg+1); agg1 seeded with y ------
#define GEMM_TR 128
#define XPITCH 132
#define GEMM_SMEM ((GEMM_TR * XPITCH + 128 * 64) * 4)

__global__ void gemm1_kernel(const float* __restrict__ x,
                             const float* __restrict__ W, int n) {
    extern __shared__ float smem[];
    float* xs = smem;                       // [128][132]
    float* ws = smem + GEMM_TR * XPITCH;    // [128][64]
    int t = threadIdx.x;
    int row0 = blockIdx.x * GEMM_TR;

    for (int i = t; i < 128 * 64 / 4; i += 256)
        ((float4*)ws)[i] = ((const float4*)W)[i];
    for (int i = t; i < GEMM_TR * 32; i += 256) {
        int r = i >> 5, c4 = i & 31;
        float4 v = make_float4(0.f, 0.f, 0.f, 0.f);
        if (row0 + r < n) v = ((const float4*)x)[(size_t)(row0 + r) * 32 + c4];
        *(float4*)&xs[r * XPITCH + c4 * 4] = v;
    }
    __syncthreads();

    int tx = t & 7;      // 8 col-groups of 8 cols (= 4 f32x2 pairs)
    int ty = t >> 3;     // 32 row-groups of 4 rows
    unsigned long long acc[4][4];
#pragma unroll
    for (int i = 0; i < 4; i++)
#pragma unroll
        for (int j = 0; j < 4; j++) acc[i][j] = 0ull;

#pragma unroll 4
    for (int k = 0; k < 128; k++) {
        const unsigned long long* w64 =
            (const unsigned long long*)(ws + k * 64 + tx * 8);
        unsigned long long b0 = w64[0], b1 = w64[1], b2 = w64[2], b3 = w64[3];
#pragma unroll
        for (int i = 0; i < 4; i++) {
            float a = xs[(ty * 4 + i) * XPITCH + k];
            unsigned long long ad;
            PACK_DUP_F32X2(ad, a);
            FMA_F32X2(acc[i][0], ad, b0, acc[i][0]);
            FMA_F32X2(acc[i][1], ad, b1, acc[i][1]);
            FMA_F32X2(acc[i][2], ad, b2, acc[i][2]);
            FMA_F32X2(acc[i][3], ad, b3, acc[i][3]);
        }
    }

#pragma unroll
    for (int i = 0; i < 4; i++) {
        int r = row0 + ty * 4 + i;
        if (r < n) {
            float d = rsqrtf(g_deg[r] + 1.0f);
            float f[8];
#pragma unroll
            for (int j = 0; j < 4; j++)
                UNPACK_F32X2(f[2 * j], f[2 * j + 1], acc[i][j]);
            float4 o0 = make_float4(f[0] * d, f[1] * d, f[2] * d, f[3] * d);
            float4 o1 = make_float4(f[4] * d, f[5] * d, f[6] * d, f[7] * d);
            size_t ofs = (size_t)r * 64 + tx * 8;
            *(float4*)&g_y[ofs] = o0;
            *(float4*)&g_y[ofs + 4] = o1;
            *(float4*)&g_agg1[ofs] = o0;       // seed self-term
            *(float4*)&g_agg1[ofs + 4] = o1;
        }
    }
}

// ---------------- K4: edge aggregation conv1 (4-edge batched, MLP=4) --------
__global__ void agg1_kernel(const int* __restrict__ row,
                            const int* __restrict__ col, int E) {
    int t = blockIdx.x * blockDim.x + threadIdx.x;
    int g = t >> 4;           // 4-edge group
    int sub = t & 15;         // 16B chunk within the 64-ch row
    int e0 = g * 4;
    if (e0 >= E) return;

    int rr[4], cc[4];
    if (e0 + 3 < E) {
        int4 r4 = __ldg((const int4*)row + g);
        int4 c4 = __ldg((const int4*)col + g);
        rr[0] = r4.x; rr[1] = r4.y; rr[2] = r4.z; rr[3] = r4.w;
        cc[0] = c4.x; cc[1] = c4.y; cc[2] = c4.z; cc[3] = c4.w;
    } else {
#pragma unroll
        for (int k = 0; k < 4; k++) {
            int e = e0 + k;
            rr[k] = (e < E) ? __ldg(row + e) : 0;
            cc[k] = (e < E) ? __ldg(col + e) : 0;
        }
    }

    const float4* yb = (const float4*)g_y;
    float4 v[4];
    bool p[4];
#pragma unroll
    for (int k = 0; k < 4; k++) {
        p[k] = (rr[k] != cc[k]);
        if (p[k]) v[k] = __ldg(yb + (size_t)rr[k] * 16 + sub);
    }
#pragma unroll
    for (int k = 0; k < 4; k++) {
        if (p[k])
            atomicAdd((float4*)&g_agg1[(size_t)cc[k] * 64 + sub * 4], v[k]);
    }
}

// ---------------- K5: x1 = tanh(agg1*dis + b1); z = (x1.W2)*dis --------------
__global__ void node1_kernel(const float* __restrict__ W2,
                             const float* __restrict__ b1, int n) {
    int gt = blockIdx.x * blockDim.x + threadIdx.x;
    int node = gt >> 5;
    int lane = gt & 31;
    if (node >= n) return;
    float dc = rsqrtf(g_deg[node] + 1.0f);
    size_t base = (size_t)node * 64 + lane * 2;
    float2 ag = *(const float2*)&g_agg1[base];
    float2 bb = *(const float2*)&b1[lane * 2];
    float v0 = tanhf(ag.x * dc + bb.x);
    float v1 = tanhf(ag.y * dc + bb.y);
    *(float2*)&g_x1[base] = make_float2(v0, v1);
    float2 w2 = *(const float2*)&W2[lane * 2];
    float dot = v0 * w2.x + v1 * w2.y;
#pragma unroll
    for (int off = 16; off; off >>= 1) dot += __shfl_xor_sync(~0u, dot, off);
    if (lane == 0) g_z[node] = dot * dc;
}

// ---------------- K6: edge aggregation conv2 (4-edge batched, MLP=4) --------
__global__ void agg2_kernel(const int* __restrict__ row,
                            const int* __restrict__ col, int E) {
    int g = blockIdx.x * blockDim.x + threadIdx.x;
    int e0 = g * 4;
    if (e0 >= E) return;
    int rr[4], cc[4];
    if (e0 + 3 < E) {
        int4 r4 = __ldg((const int4*)row + g);
        int4 c4 = __ldg((const int4*)col + g);
        rr[0] = r4.x; rr[1] = r4.y; rr[2] = r4.z; rr[3] = r4.w;
        cc[0] = c4.x; cc[1] = c4.y; cc[2] = c4.z; cc[3] = c4.w;
    } else {
#pragma unroll
        for (int k = 0; k < 4; k++) {
            int e = e0 + k;
            rr[k] = (e < E) ? row[e] : 0;
            cc[k] = (e < E) ? col[e] : 0;
        }
    }
    float zv[4];
    bool p[4];
#pragma unroll
    for (int k = 0; k < 4; k++) {
        p[k] = (rr[k] != cc[k]);
        if (p[k]) zv[k] = __ldg(&g_z[rr[k]]);
    }
#pragma unroll
    for (int k = 0; k < 4; k++)
        if (p[k]) atomicAdd(&g_agg2[cc[k]], zv[k]);
}

// ---------------- K9: fused x2 + sort-pool(top-30) + CNN head + MLP ---------
// start/cnt come from binary search on the SORTED batch array; x2 computed
// in-block (identical math to the old node2_kernel).
__device__ __forceinline__ int lower_bound_i(const int* __restrict__ b,
                                             int n, int v) {
    int lo = 0, hi = n;
    while (lo < hi) {
        int m = (lo + hi) >> 1;
        if (__ldg(b + m) < v) lo = m + 1; else hi = m;
    }
    return lo;
}

__global__ void head_kernel(const int* __restrict__ batch,
                            const float* __restrict__ b2,
                            const float* __restrict__ w3, const float* __restrict__ b3,
                            const float* __restrict__ w4, const float* __restrict__ b4,
                            const float* __restrict__ fw1, const float* __restrict__ fb1,
                            const float* __restrict__ fw2, const float* __restrict__ fb2,
                            float* __restrict__ out, int B, int n) {
    __shared__ float sc[SEGMAX];    // selection scores (destroyed)
    __shared__ float x2c[SEGMAX];   // preserved x2 copy
    __shared__ int sel[KTOP];
    __shared__ float p[PLEN];
    __shared__ float c3[320];
    __shared__ float pl[160];
    __shared__ float h[192];
    __shared__ float ll[128];
    __shared__ float o[18];
    __shared__ unsigned long long redw[8];

    int g = blockIdx.x;
    int t = threadIdx.x;
    int lane = t & 31;
    int warp = t >> 5;

    // segment bounds via binary search on sorted batch (redundant per thread)
    int start = lower_bound_i(batch, n, g);
    int end   = lower_bound_i(batch, n, g + 1);
    int cnt = min(end - start, SEGMAX);
    int ksel = min(cnt, KTOP);

    // fused node2: x2 = tanh((agg2 + z) * rsqrt(deg+1) + b2)
    float b2v = b2[0];
    for (int i = t; i < cnt; i += 256) {
        int node = start + i;
        float dc = rsqrtf(g_deg[node] + 1.0f);
        float v = tanhf((g_agg2[node] + g_z[node]) * dc + b2v);
        sc[i] = v;
        x2c[i] = v;
    }
    __syncthreads();

    // iterative stable top-K: max score, tie -> lowest index (matches lexsort)
    for (int j = 0; j < ksel; j++) {
        unsigned long long best = 0ull;
        for (int i = t; i < cnt; i += 256) {
            unsigned u = __float_as_uint(sc[i]);
            u = (u & 0x80000000u) ? ~u : (u | 0x80000000u);
            unsigned long long key =
                ((unsigned long long)u << 32) | (unsigned)(~i);
            if (key > best) best = key;
        }
#pragma unroll
        for (int off = 16; off; off >>= 1) {
            unsigned long long o2 = __shfl_xor_sync(~0u, best, off);
            best = max(best, o2);
        }
        if (lane == 0) redw[warp] = best;
        __syncthreads();
        if (warp == 0) {
            unsigned long long b2k = (lane < 8) ? redw[lane] : 0ull;
#pragma unroll
            for (int off = 4; off; off >>= 1) {
                unsigned long long o2 = __shfl_xor_sync(~0u, b2k, off);
                b2k = max(b2k, o2);
            }
            if (lane == 0) {
                int pos = (int)(~(unsigned)(b2k & 0xFFFFFFFFull));
                sel[j] = pos;                  // local position in segment
                sc[pos] = -CUDART_INF_F;
            }
        }
        __syncthreads();
    }

    for (int idx = t; idx < PLEN; idx += 256) {
        int j = idx / 65, c = idx % 65;
        float v = 0.f;
        if (j < ksel) {
            int pos = sel[j];
            v = (c < 64) ? g_x1[(size_t)(start + pos) * 64 + c] : x2c[pos];
        }
        p[idx] = v;
    }
    __syncthreads();

    for (int idx = t; idx < 320; idx += 256) {
        int oc = idx / 20, tt = idx % 20;
        float s = b3[oc];
        const float* w = w3 + oc * 97;
        const float* pp = p + tt * 97;
#pragma unroll 1
        for (int i = 0; i < 97; i++) s += pp[i] * w[i];
        c3[oc * 20 + tt] = fmaxf(s, 0.f);
    }
    __syncthreads();

    for (int idx = t; idx < 160; idx += 256) {
        int oc = idx / 10, tt = idx % 10;
        pl[idx] = fmaxf(c3[oc * 20 + 2 * tt], c3[oc * 20 + 2 * tt + 1]);
    }
    __syncthreads();

    for (int idx = t; idx < 192; idx += 256) {
        int oc = idx / 6, tt = idx % 6;
        float s = b4[oc];
#pragma unroll
        for (int ic = 0; ic < 16; ic++)
#pragma unroll
            for (int i = 0; i < 5; i++)
                s += pl[ic * 10 + tt + i] * w4[oc * 80 + ic * 5 + i];
        h[idx] = fmaxf(s, 0.f);
    }
    __syncthreads();

    for (int j = t; j < 128; j += 256) {
        float s = fb1[j];
#pragma unroll 4
        for (int i = 0; i < 192; i++) s += h[i] * fw1[i * 128 + j];
        float r = fmaxf(s, 0.f);
        ll[j] = r;
        out[(size_t)2 * B * 18 + (size_t)g * 128 + j] = r;
    }
    __syncthreads();

    for (int j = t; j < 18; j += 256) {
        float s = fb2[j];
#pragma unroll 4
        for (int i = 0; i < 128; i++) s += ll[i] * fw2[i * 18 + j];
        o[j] = s;
        out[(size_t)B * 18 + (size_t)g * 18 + j] = s;
    }
    __syncthreads();

    if (t == 0) {
        float m = o[0];
        for (int j = 1; j < 18; j++) m = fmaxf(m, o[j]);
        float se = 0.f;
        for (int j = 0; j < 18; j++) se += expf(o[j] - m);
        float lse = logf(se) + m;
        for (int j = 0; j < 18; j++) out[(size_t)g * 18 + j] = o[j] - lse;
    }
}

// ---------------- launch ----------------------------------------------------
extern "C" void kernel_launch(void* const* d_in, const int* in_sizes, int n_in,
                              void* d_out, int out_size) {
    const float* x    = (const float*)d_in[0];
    const int* ei     = (const int*)d_in[1];
    const int* batch  = (const int*)d_in[2];
    const float* W1   = (const float*)d_in[4];
    const float* b1   = (const float*)d_in[5];
    const float* W2   = (const float*)d_in[6];
    const float* b2   = (const float*)d_in[7];
    const float* w3   = (const float*)d_in[8];
    const float* b3   = (const float*)d_in[9];
    const float* w4   = (const float*)d_in[10];
    const float* b4   = (const float*)d_in[11];
    const float* fw1  = (const float*)d_in[12];
    const float* fb1  = (const float*)d_in[13];
    const float* fw2  = (const float*)d_in[14];
    const float* fb2  = (const float*)d_in[15];
    float* out = (float*)d_out;

    int n = in_sizes[0] / 128;
    int E = in_sizes[1] / 2;
    int B = out_size / 164;   // 18 + 18 + 128
    const int* row = ei;
    const int* col = ei + E;
    int EG = (E + 3) / 4;     // 4-edge groups

    zero_kernel<<<(n + 255) / 256, 256>>>(n);
    deg_kernel<<<(EG + 255) / 256, 256>>>(row, col, E);

    cudaFuncSetAttribute(gemm1_kernel,
                         cudaFuncAttributeMaxDynamicSharedMemorySize, GEMM_SMEM);
    gemm1_kernel<<<(n + GEMM_TR - 1) / GEMM_TR, 256, GEMM_SMEM>>>(x, W1, n);

    {
        long long tot = (long long)EG * 16;
        int blocks = (int)((tot + 255) / 256);
        agg1_kernel<<<blocks, 256>>>(row, col, E);
    }

    node1_kernel<<<(n * 32 + 255) / 256, 256>>>(W2, b1, n);
    agg2_kernel<<<(EG + 255) / 256, 256>>>(row, col, E);
    head_kernel<<<B, 256>>>(batch, b2, w3, b3, w4, b4,
                            fw1, fb1, fw2, fb2, out, B, n);
}